// round 10
// baseline (speedup 1.0000x reference)
#include <cuda_runtime.h>
#include <cuda_fp16.h>
#include <cstdint>

#define DFEAT 64
#define NREL 16
#define NCOLS 1088           // (NREL+1)*64 packed weight cols
#define NNODE_MAX 100000
#define EDGE_MAX  1500000
#define NBLK_MAX  512

typedef unsigned long long u64;

// ---------------------------------------------------------------------------
// Scratch (allocation-free, __device__ globals)
// ---------------------------------------------------------------------------
__device__ __half  g_Xhi[(size_t)NNODE_MAX * DFEAT];    // layer-1 operand (12.8 MB)
__device__ __half  g_Xlo[(size_t)NNODE_MAX * DFEAT];
__device__ __half  g_Xhi2[(size_t)NNODE_MAX * DFEAT];   // layer-2 operand
__device__ __half  g_Xlo2[(size_t)NNODE_MAX * DFEAT];
__device__ __half  g_Bhi[2 * NCOLS * DFEAT];            // double-buffered weights
__device__ __half  g_Blo[2 * NCOLS * DFEAT];
// CSR keyed (rel*N + dst)
__device__ int g_cnt[NREL * NNODE_MAX];
__device__ int g_indptr[NREL * NNODE_MAX + 1];
__device__ int g_cursor[NREL * NNODE_MAX];
__device__ int g_bsum[NBLK_MAX];
__device__ int g_edata[EDGE_MAX];    // src only

// ---------------------------------------------------------------------------
__device__ __forceinline__ uint32_t smem_to_u32(const void* p) {
    uint32_t a;
    asm("{ .reg .u64 t; cvta.to.shared.u64 t, %1; cvt.u32.u64 %0, t; }" : "=r"(a) : "l"(p));
    return a;
}
__device__ __forceinline__ void ldsm4(uint32_t* r, uint32_t a) {
    asm volatile("ldmatrix.sync.aligned.m8n8.x4.shared.b16 {%0,%1,%2,%3}, [%4];"
                 : "=r"(r[0]), "=r"(r[1]), "=r"(r[2]), "=r"(r[3]) : "r"(a));
}
__device__ __forceinline__ void mma_fp16(float* d, const uint32_t* a, const uint32_t* b) {
    asm volatile("mma.sync.aligned.m16n8k16.row.col.f32.f16.f16.f32 "
                 "{%0,%1,%2,%3}, {%4,%5,%6,%7}, {%8,%9}, {%0,%1,%2,%3};"
                 : "+f"(d[0]), "+f"(d[1]), "+f"(d[2]), "+f"(d[3])
                 : "r"(a[0]), "r"(a[1]), "r"(a[2]), "r"(a[3]), "r"(b[0]), "r"(b[1]));
}

// ---------------------------------------------------------------------------
// CSR build: key = et*N + dst ; payload = src
// ---------------------------------------------------------------------------
__global__ void hist_k(const int* __restrict__ ei, const int* __restrict__ et,
                       int E, int N) {
    int e = blockIdx.x * blockDim.x + threadIdx.x;
    if (e >= E) return;
    atomicAdd(&g_cnt[et[e] * N + ei[E + e]], 1);
}
__global__ void scan1(int M) {   // 4096 elements per block
    __shared__ int sh[1024];
    int t = threadIdx.x;
    int base = blockIdx.x * 4096 + t * 4;
    int v0 = 0, v1 = 0, v2 = 0, v3 = 0;
    if (base + 3 < M) {
        int4 v = *(const int4*)(g_cnt + base);
        v0 = v.x; v1 = v.y; v2 = v.z; v3 = v.w;
    } else {
        if (base     < M) v0 = g_cnt[base];
        if (base + 1 < M) v1 = g_cnt[base + 1];
        if (base + 2 < M) v2 = g_cnt[base + 2];
        if (base + 3 < M) v3 = g_cnt[base + 3];
    }
    int s = v0 + v1 + v2 + v3;
    sh[t] = s;
    __syncthreads();
    for (int off = 1; off < 1024; off <<= 1) {
        int a = (t >= off) ? sh[t - off] : 0;
        __syncthreads();
        sh[t] += a;
        __syncthreads();
    }
    int excl = sh[t] - s;
    if (base     < M) g_indptr[base]     = excl;
    if (base + 1 < M) g_indptr[base + 1] = excl + v0;
    if (base + 2 < M) g_indptr[base + 2] = excl + v0 + v1;
    if (base + 3 < M) g_indptr[base + 3] = excl + v0 + v1 + v2;
    if (t == 1023) g_bsum[blockIdx.x] = sh[1023];
}
__global__ void scan2(int nb) {
    __shared__ int sh[NBLK_MAX];
    int t = threadIdx.x;
    int v = (t < nb) ? g_bsum[t] : 0;
    sh[t] = v;
    __syncthreads();
    for (int off = 1; off < NBLK_MAX; off <<= 1) {
        int a = (t >= off) ? sh[t - off] : 0;
        __syncthreads();
        sh[t] += a;
        __syncthreads();
    }
    if (t < nb) g_bsum[t] = sh[t] - v;
}
__global__ void scan3(int M, int E) {
    int t = threadIdx.x;
    int base = blockIdx.x * 4096 + t * 4;
    int add = g_bsum[blockIdx.x];
#pragma unroll
    for (int j = 0; j < 4; j++) {
        if (base + j < M) {
            int v = g_indptr[base + j] + add;
            g_indptr[base + j] = v;
            g_cursor[base + j] = v;
        }
    }
    if (blockIdx.x == 0 && t == 0) g_indptr[M] = E;
}
__global__ void fill_k(const int* __restrict__ ei, const int* __restrict__ et,
                       int E, int N) {
    int e = blockIdx.x * blockDim.x + threadIdx.x;
    if (e >= E) return;
    int pos = atomicAdd(&g_cursor[et[e] * N + ei[E + e]], 1);
    g_edata[pos] = ei[e];
}

// ---------------------------------------------------------------------------
// fp16 hi/lo conversion (layer-1 input)
// ---------------------------------------------------------------------------
__global__ void conv_fp16(const float* __restrict__ src, int total4) {
    int idx4 = blockIdx.x * blockDim.x + threadIdx.x;
    if (idx4 >= total4) return;
    float4 v = *(const float4*)(src + (size_t)idx4 * 4);
    float f[4] = {v.x, v.y, v.z, v.w};
    union { __half b[4]; uint2 u; } hi, lo;
#pragma unroll
    for (int i = 0; i < 4; i++) {
        hi.b[i] = __float2half_rn(f[i]);
        lo.b[i] = __float2half_rn(f[i] - __half2float(hi.b[i]));
    }
    *(uint2*)(g_Xhi + (size_t)idx4 * 4) = hi.u;
    *(uint2*)(g_Xlo + (size_t)idx4 * 4) = lo.u;
}

// ---------------------------------------------------------------------------
// Pack B[c][k] = Wcat[k][c] (fp16 hi/lo) into buffer `buf`
// ---------------------------------------------------------------------------
__global__ void pack_wb(const float* __restrict__ W, const float* __restrict__ sw, int buf) {
    int idx = blockIdx.x * blockDim.x + threadIdx.x;
    if (idx >= NCOLS * DFEAT) return;
    int c = idx / DFEAT;
    int k = idx - c * DFEAT;
    float v;
    if (c < DFEAT) {
        v = sw[k * DFEAT + c];
    } else {
        int rc = c - DFEAT;
        int r = rc >> 6, j = rc & 63;
        v = W[r * DFEAT * DFEAT + k * DFEAT + j];
    }
    __half hi = __float2half_rn(v);
    __half lo = __float2half_rn(v - __half2float(hi));
    g_Bhi[buf * NCOLS * DFEAT + idx] = hi;
    g_Blo[buf * NCOLS * DFEAT + idx] = lo;
}

// ---------------------------------------------------------------------------
// Fused layer: per 128-dst block, for each rel: aggregate Xh[src] rows into
// smem Z tile (fp32 regs -> fp16), MMA vs W[rel]; accumulate all rels + self
// (3-term) in registers; epilogue bias (+residual) + relu.
// mode=1: layer 1 (residual; outputs fp16 hi/lo operand for layer 2)
// mode=0: layer 2 (no residual; outputs fp32)
// ---------------------------------------------------------------------------
#define ASTRIDE 72
#define SM_ZH 0                          // 128 x 144 B = 18432
#define SM_BH 18432                      // 64 x 144 B  = 9216
#define SM_BL (18432 + 9216)             // 9216
#define SMEM_BYTES (18432 + 9216 + 9216) // 36864

__global__ void __launch_bounds__(256) fused_layer(
    const __half* __restrict__ Xh, const __half* __restrict__ Xl,
    const float* __restrict__ xres, const float* __restrict__ bias,
    __half* __restrict__ oXh, __half* __restrict__ oXl,
    float* __restrict__ oF,
    int N, int mode, int wbuf)
{
    __shared__ char smem[SMEM_BYTES];
    const uint32_t sb = smem_to_u32(smem);
    const int t = threadIdx.x;
    const int wid = t >> 5, lid = t & 31;
    const int n0 = blockIdx.x * 128;
    const size_t wb0 = (size_t)wbuf * NCOLS * DFEAT;
    const uint4* BhiV = (const uint4*)(g_Bhi + wb0);
    const uint4* BloV = (const uint4*)(g_Blo + wb0);
    const uint4* XhV  = (const uint4*)Xh;
    const uint4* XlV  = (const uint4*)Xl;

    const int wr = wid >> 1, wc = wid & 1;
    const int sub = lid >> 3, l7 = lid & 7;
    const int a_row = wr * 32 + ((sub & 1) << 3) + l7;
    const int a_kof = (sub >> 1) << 3;
    const int b_row = wc * 32 + ((sub >> 1) << 3) + l7;
    const int b_kof = (sub & 1) << 3;
    const int g  = lid >> 2, tg = lid & 3;

    const int sl = lid >> 3;          // sublane 0..3 (4 dsts in flight)
    const int c8 = (lid & 7) * 8;     // 8 halves per lane

    float acc[2][4][4];
#pragma unroll
    for (int mi = 0; mi < 2; mi++)
#pragma unroll
        for (int nt = 0; nt < 4; nt++)
#pragma unroll
            for (int q = 0; q < 4; q++) acc[mi][nt][q] = 0.0f;

    // ================= relation loop =================
    for (int rel = 0; rel < NREL; rel++) {
        __syncthreads();    // previous MMA done reading ZH/BH
        // load W[rel] hi tile
        {
            const int cg0 = (1 + rel) * 64;
#pragma unroll
            for (int i = t; i < 512; i += 256) {
                int row = i >> 3, q = i & 7;
                *(uint4*)(smem + SM_BH + row * 144 + q * 16) = BhiV[(size_t)(cg0 + row) * 8 + q];
            }
        }
        // aggregate: 4 rounds x (8 warps x 4 sublane-dsts)
#pragma unroll
        for (int k4 = 0; k4 < 4; k4++) {
            int d = k4 * 32 + wid * 4 + sl;
            int node = n0 + d;
            float fa[8];
#pragma unroll
            for (int q = 0; q < 8; q++) fa[q] = 0.0f;
            if (node < N) {
                int key = rel * N + node;
                int s  = g_indptr[key];
                int e2 = g_indptr[key + 1];
                for (int i = s; i < e2; i++) {
                    int src = g_edata[i];
                    uint4 raw = *(const uint4*)(Xh + (size_t)src * DFEAT + c8);
                    const __half2* hp = (const __half2*)&raw;
#pragma unroll
                    for (int q = 0; q < 4; q++) {
                        float2 f = __half22float2(hp[q]);
                        fa[2 * q]     += f.x;
                        fa[2 * q + 1] += f.y;
                    }
                }
            }
            uint4 o;
            __half2 h0 = __floats2half2_rn(fa[0], fa[1]);
            __half2 h1 = __floats2half2_rn(fa[2], fa[3]);
            __half2 h2 = __floats2half2_rn(fa[4], fa[5]);
            __half2 h3 = __floats2half2_rn(fa[6], fa[7]);
            o.x = *(uint32_t*)&h0; o.y = *(uint32_t*)&h1;
            o.z = *(uint32_t*)&h2; o.w = *(uint32_t*)&h3;
            *(uint4*)(smem + SM_ZH + d * 144 + c8 * 2) = o;
        }
        __syncthreads();
        // MMA: Z x W[rel], 1-term
#pragma unroll
        for (int ks = 0; ks < 4; ks++) {
            const int k0 = ks * 16;
            uint32_t ah[2][4], bh[2][4];
#pragma unroll
            for (int mi = 0; mi < 2; mi++)
                ldsm4(ah[mi], sb + SM_ZH + (uint32_t)((a_row + mi * 16) * ASTRIDE + k0 + a_kof) * 2);
#pragma unroll
            for (int nj = 0; nj < 2; nj++)
                ldsm4(bh[nj], sb + SM_BH + (uint32_t)((b_row + nj * 16) * ASTRIDE + k0 + b_kof) * 2);
#pragma unroll
            for (int mi = 0; mi < 2; mi++)
#pragma unroll
                for (int nt = 0; nt < 4; nt++)
                    mma_fp16(acc[mi][nt], ah[mi], &bh[nt >> 1][(nt & 1) * 2]);
        }
    }

    // ================= self transform (3-term) =================
    __syncthreads();
#pragma unroll
    for (int i = t; i < 1024; i += 256) {
        int row = i >> 3, q = i & 7;
        int n = n0 + row; if (n >= N) n = N - 1;
        *(uint4*)(smem + SM_ZH + row * 144 + q * 16) = XhV[(size_t)n * 8 + q];
    }
#pragma unroll
    for (int i = t; i < 512; i += 256) {
        int row = i >> 3, q = i & 7;
        *(uint4*)(smem + SM_BH + row * 144 + q * 16) = BhiV[(size_t)row * 8 + q];
        *(uint4*)(smem + SM_BL + row * 144 + q * 16) = BloV[(size_t)row * 8 + q];
    }
    __syncthreads();
#pragma unroll
    for (int ks = 0; ks < 4; ks++) {
        const int k0 = ks * 16;
        uint32_t ah[2][4], bh[2][4], bl[2][4];
#pragma unroll
        for (int mi = 0; mi < 2; mi++)
            ldsm4(ah[mi], sb + SM_ZH + (uint32_t)((a_row + mi * 16) * ASTRIDE + k0 + a_kof) * 2);
#pragma unroll
        for (int nj = 0; nj < 2; nj++) {
            ldsm4(bh[nj], sb + SM_BH + (uint32_t)((b_row + nj * 16) * ASTRIDE + k0 + b_kof) * 2);
            ldsm4(bl[nj], sb + SM_BL + (uint32_t)((b_row + nj * 16) * ASTRIDE + k0 + b_kof) * 2);
        }
#pragma unroll
        for (int mi = 0; mi < 2; mi++)
#pragma unroll
            for (int nt = 0; nt < 4; nt++) {
                mma_fp16(acc[mi][nt], ah[mi], &bh[nt >> 1][(nt & 1) * 2]);
                mma_fp16(acc[mi][nt], ah[mi], &bl[nt >> 1][(nt & 1) * 2]);
            }
    }
    __syncthreads();
#pragma unroll
    for (int i = t; i < 1024; i += 256) {
        int row = i >> 3, q = i & 7;
        int n = n0 + row; if (n >= N) n = N - 1;
        *(uint4*)(smem + SM_ZH + row * 144 + q * 16) = XlV[(size_t)n * 8 + q];
    }
    __syncthreads();
#pragma unroll
    for (int ks = 0; ks < 4; ks++) {
        const int k0 = ks * 16;
        uint32_t ah[2][4], bh[2][4];
#pragma unroll
        for (int mi = 0; mi < 2; mi++)
            ldsm4(ah[mi], sb + SM_ZH + (uint32_t)((a_row + mi * 16) * ASTRIDE + k0 + a_kof) * 2);
#pragma unroll
        for (int nj = 0; nj < 2; nj++)
            ldsm4(bh[nj], sb + SM_BH + (uint32_t)((b_row + nj * 16) * ASTRIDE + k0 + b_kof) * 2);
#pragma unroll
        for (int mi = 0; mi < 2; mi++)
#pragma unroll
            for (int nt = 0; nt < 4; nt++)
                mma_fp16(acc[mi][nt], ah[mi], &bh[nt >> 1][(nt & 1) * 2]);
    }

    // ================= epilogue =================
#pragma unroll
    for (int mi = 0; mi < 2; mi++)
#pragma unroll
        for (int hf = 0; hf < 2; hf++) {
            int row = n0 + wr * 32 + mi * 16 + g + hf * 8;
            if (row >= N) continue;
#pragma unroll
            for (int nt = 0; nt < 4; nt++) {
                int cl = wc * 32 + nt * 8 + tg * 2;
                float v0 = acc[mi][nt][hf * 2 + 0] + bias[cl];
                float v1 = acc[mi][nt][hf * 2 + 1] + bias[cl + 1];
                if (mode) {
                    v0 += xres[(size_t)row * DFEAT + cl];
                    v1 += xres[(size_t)row * DFEAT + cl + 1];
                    float rx = fmaxf(v0, 0.0f), ry = fmaxf(v1, 0.0f);
                    __half h0 = __float2half_rn(rx), h1 = __float2half_rn(ry);
                    __half l0 = __float2half_rn(rx - __half2float(h0));
                    __half l1 = __float2half_rn(ry - __half2float(h1));
                    __half2 hh = __halves2half2(h0, h1);
                    __half2 ll = __halves2half2(l0, l1);
                    *(uint32_t*)(oXh + (size_t)row * DFEAT + cl) = *(uint32_t*)&hh;
                    *(uint32_t*)(oXl + (size_t)row * DFEAT + cl) = *(uint32_t*)&ll;
                } else {
                    float rx = fmaxf(v0, 0.0f), ry = fmaxf(v1, 0.0f);
                    *(float2*)(oF + (size_t)row * DFEAT + cl) = make_float2(rx, ry);
                }
            }
        }
}

// ---------------------------------------------------------------------------
extern "C" void kernel_launch(void* const* d_in, const int* in_sizes, int n_in,
                              void* d_out, int out_size) {
    const float* x   = (const float*)d_in[0];
    const int*   ei  = (const int*)d_in[1];
    const int*   et  = (const int*)d_in[2];
    const float* W1  = (const float*)d_in[3];
    const float* sw1 = (const float*)d_in[4];
    const float* b1  = (const float*)d_in[5];
    const float* W2  = (const float*)d_in[6];
    const float* sw2 = (const float*)d_in[7];
    const float* b2  = (const float*)d_in[8];
    float* out = (float*)d_out;

    const int N = in_sizes[0] / DFEAT;
    const int E = in_sizes[2];
    const int total4 = N * (DFEAT / 4);
    const int M = NREL * N;
    const int nb = (M + 4095) / 4096;

    __half *xh1, *xl1, *xh2, *xl2;
    cudaGetSymbolAddress((void**)&xh1, g_Xhi);
    cudaGetSymbolAddress((void**)&xl1, g_Xlo);
    cudaGetSymbolAddress((void**)&xh2, g_Xhi2);
    cudaGetSymbolAddress((void**)&xl2, g_Xlo2);
    int* cntptr = nullptr;
    cudaGetSymbolAddress((void**)&cntptr, g_cnt);

    static cudaStream_t s1 = nullptr;
    static cudaEvent_t ev_fork = nullptr, ev_join = nullptr;
    if (!s1) {
        cudaStreamCreateWithFlags(&s1, cudaStreamNonBlocking);
        cudaEventCreateWithFlags(&ev_fork, cudaEventDisableTiming);
        cudaEventCreateWithFlags(&ev_join, cudaEventDisableTiming);
    }

    int pack_blocks = (NCOLS * DFEAT + 255) / 256;
    int el_blocks   = (total4 + 255) / 256;
    int e_blocks    = (E + 255) / 256;
    int row_blocks  = (N + 127) / 128;

    // ---- side stream: CSR build + layer-2 weight pack ----
    cudaEventRecord(ev_fork, 0);
    cudaStreamWaitEvent(s1, ev_fork, 0);
    cudaMemsetAsync(cntptr, 0, (size_t)M * sizeof(int), s1);
    hist_k<<<e_blocks, 256, 0, s1>>>(ei, et, E, N);
    scan1<<<nb, 1024, 0, s1>>>(M);
    scan2<<<1, NBLK_MAX, 0, s1>>>(nb);
    scan3<<<nb, 1024, 0, s1>>>(M, E);
    fill_k<<<e_blocks, 256, 0, s1>>>(ei, et, E, N);
    pack_wb<<<pack_blocks, 256, 0, s1>>>(W2, sw2, 1);
    cudaEventRecord(ev_join, s1);

    // ---- main stream ----
    conv_fp16<<<el_blocks, 256>>>(x, total4);
    pack_wb<<<pack_blocks, 256>>>(W1, sw1, 0);
    cudaStreamWaitEvent(0, ev_join, 0);

    // layer 1 (residual; emits fp16 hi/lo operand for layer 2)
    fused_layer<<<row_blocks, 256>>>(xh1, xl1, x, b1, xh2, xl2, nullptr, N, 1, 0);
    // layer 2 (no residual; fp32 output)
    fused_layer<<<row_blocks, 256>>>(xh2, xl2, nullptr, b2, nullptr, nullptr, out, N, 0, 1);
}